// round 5
// baseline (speedup 1.0000x reference)
#include <cuda_runtime.h>
#include <stdint.h>

#define HH 2048
#define WW 2048
#define NPIX (HH * WW)

#define TW 32                    // tile width
#define TH 16                    // tile height
#define SW (TW + 2)              // 34 (halo)
#define SH (TH + 2)              // 18 (halo)
#define NSLOT (SW * SH)          // 612

#define NBX 64                   // tiles per row (bits in a mask word)
#define NBY 128                  // tile rows
#define NB  (NBX * NBY)          // 8192
#define NITER 100

__device__ float g_scratch[NPIX];
__device__ unsigned long long g_chmask[2][NBY];   // changed bits, per parity
__device__ unsigned long long g_posmask[NBY];     // possible bits
__device__ int g_needflag[2];
__device__ unsigned int g_arrive;                 // zero-init; restored each barrier
__device__ unsigned int g_release;                // generation counter
__device__ int g_stop;

// ---------------------------------------------------------------------------
// Threefry-2x32, 20 rounds — exact transcription of jax._src.prng
// ---------------------------------------------------------------------------
__host__ __device__ __forceinline__ uint32_t rotl32(uint32_t v, uint32_t r) {
#ifdef __CUDA_ARCH__
    return __funnelshift_l(v, v, r);
#else
    return (v << r) | (v >> (32u - r));
#endif
}

__host__ __device__ __forceinline__ void tf2x32(uint32_t k0, uint32_t k1,
                                                uint32_t x0, uint32_t x1,
                                                uint32_t& o0, uint32_t& o1) {
    uint32_t ks2 = k0 ^ k1 ^ 0x1BD11BDAu;
    x0 += k0; x1 += k1;
#define TF_R(r) { x0 += x1; x1 = rotl32(x1, r); x1 ^= x0; }
    TF_R(13u) TF_R(15u) TF_R(26u) TF_R(6u)
    x0 += k1;  x1 += ks2 + 1u;
    TF_R(17u) TF_R(29u) TF_R(16u) TF_R(24u)
    x0 += ks2; x1 += k0 + 2u;
    TF_R(13u) TF_R(15u) TF_R(26u) TF_R(6u)
    x0 += k0;  x1 += k1 + 3u;
    TF_R(17u) TF_R(29u) TF_R(16u) TF_R(24u)
    x0 += k1;  x1 += ks2 + 4u;
    TF_R(13u) TF_R(15u) TF_R(26u) TF_R(6u)
    x0 += ks2; x1 += k0 + 5u;
#undef TF_R
    o0 = x0; o1 = x1;
}

// Partitionable-mode random bits for flat index p: counter=(0,p); bits=o0^o1
__device__ __forceinline__ uint32_t pbits(uint32_t k0, uint32_t k1, uint32_t p) {
    uint32_t o0, o1;
    tf2x32(k0, k1, 0u, p, o0, o1);
    return o0 ^ o1;
}

__device__ __forceinline__ float bits_to_uniform(uint32_t bits) {
    return __fsub_rn(__uint_as_float((bits >> 9) | 0x3f800000u), 1.0f);
}

// ---------------------------------------------------------------------------
// Grid-wide barrier (all blocks co-resident by construction).
// Last arriver zeroes next-parity masks + evaluates the stop condition.
// ---------------------------------------------------------------------------
__device__ __forceinline__ void grid_barrier(int nblocks, int zeroPar, int checkPar) {
    __syncthreads();
    if (threadIdx.x == 0) {
        __threadfence();
        volatile unsigned* rel = &g_release;
        unsigned gen = *rel;
        if (atomicAdd(&g_arrive, 1u) == (unsigned)(nblocks - 1)) {
            g_arrive = 0u;
            if (zeroPar >= 0) {
                #pragma unroll 8
                for (int r = 0; r < NBY; r++) g_chmask[zeroPar][r] = 0ull;
                g_needflag[zeroPar] = 0;
                if (g_needflag[checkPar] == 0) g_stop = 1;
            }
            __threadfence();
            *rel = gen + 1u;
        } else {
            while (*rel == gen) __nanosleep(64);
        }
        __threadfence();
    }
    __syncthreads();
}

// ---------------------------------------------------------------------------
// The whole problem in one persistent kernel.
// ---------------------------------------------------------------------------
__global__ __launch_bounds__(256, 6)
void persist_kernel(const float* __restrict__ seed,
                    const float* __restrict__ hab,
                    const float* __restrict__ good,
                    float* __restrict__ dout, int nblocks) {
    __shared__ float xs[SH][SW];                 // raw x (tile + halo)
    __shared__ float ys[SH][SW];                 // noised x (maxpool operand)
    __shared__ unsigned long long s_ch[NBY];     // changed[prev] snapshot
    __shared__ unsigned long long s_pos[NBY];    // possible snapshot
    __shared__ unsigned s_rowpos[TH];

    const int tid = threadIdx.x;
    const int tx = tid & 31;
    const int ty = tid >> 5;
    float* scratch = g_scratch;

    // ==== init phase: x0 = seed*hab*good into dout; reset masks/flags ====
    {
        const float4* s4 = (const float4*)seed;
        const float4* h4 = (const float4*)hab;
        const float4* g4 = (const float4*)good;
        float4* o4 = (float4*)dout;
        for (int idx = blockIdx.x * 256 + tid; idx < NPIX / 4; idx += nblocks * 256) {
            float4 s = s4[idx], h = h4[idx], g = g4[idx], o;
            o.x = __fmul_rn(__fmul_rn(s.x, h.x), g.x);
            o.y = __fmul_rn(__fmul_rn(s.y, h.y), g.y);
            o.z = __fmul_rn(__fmul_rn(s.z, h.z), g.z);
            o.w = __fmul_rn(__fmul_rn(s.w, h.w), g.w);
            o4[idx] = o;
        }
        if (blockIdx.x == 0) {
            if (tid < NBY) {
                g_chmask[1][tid] = ~0ull;   // iter 0 (prev parity 1): force all
                g_chmask[0][tid] = 0ull;
                g_posmask[tid]   = 0ull;
            }
            if (tid == 0) { g_needflag[0] = 0; g_needflag[1] = 0; g_stop = 0; }
        }
    }
    grid_barrier(nblocks, -1, -1);

    // ==== iteration loop ====
    for (int i = 0; i < NITER; i++) {
        if (*(volatile int*)&g_stop) break;     // x frozen; both buffers final

        const int cur = i & 1, prev = cur ^ 1;
        const float* xin = (i & 1) ? scratch : dout;
        float*       xo  = (i & 1) ? dout    : scratch;

        // per-iteration key schedule (fold_in + partitionable split)
        uint32_t f0, f1, k1a, k1b, k2a, k2b;
        tf2x32(0u, 42u, 0u, (uint32_t)i, f0, f1);
        tf2x32(f0, f1, 0u, 0u, k1a, k1b);
        tf2x32(f0, f1, 0u, 1u, k2a, k2b);

        // snapshot masks to smem (stable: writes this iter go to cur parity,
        // and possible bits we consult belong only to tiles this block owns)
        if (tid < NBY) s_ch[tid] = g_chmask[prev][tid];
        else if (tid < 2 * NBY) s_pos[tid - NBY] = g_posmask[tid - NBY];
        __syncthreads();

        int sawNeed = 0;
        for (int t = blockIdx.x; t < NB; t += nblocks) {
            const int by = t >> 6, bx = t & 63;
            unsigned long long nbm = s_ch[by];
            if (by > 0)       nbm |= s_ch[by - 1];
            if (by < NBY - 1) nbm |= s_ch[by + 1];
            unsigned long long colm = (bx == 0) ? 3ull : (7ull << (bx - 1));
            bool need = ((nbm & colm) != 0ull) || (((s_pos[by] >> bx) & 1ull) != 0ull);
            if (!need) continue;                // uniform across block
            sawNeed = 1;
            const int selfchg = (int)((s_ch[by] >> bx) & 1ull);
            const int c0 = bx * TW, r0 = by * TH;

            __syncthreads();                    // smem reuse barrier

            // ==== load raw x tile + halo ====
            #pragma unroll
            for (int k = 0; k < 3; k++) {
                int s = tid + k * 256;
                if (s < NSLOT) {
                    int j = s / SW, ii = s % SW;
                    int r = r0 - 1 + j, c = c0 - 1 + ii;
                    bool ok = (r >= 0) && (r < HH) && (c >= 0) && (c < WW);
                    xs[j][ii] = ok ? xin[r * WW + c] : 0.0f;
                }
            }
            __syncthreads();

            // ==== per-cell possible upper bound (noise factor <= 1.0f) ====
            float xx[2], gd[2];
            bool  pos[2];
            #pragma unroll
            for (int k = 0; k < 2; k++) {
                int jj = 1 + ty + k * 8, ii = 1 + tx;
                float M = xs[jj - 1][ii - 1];
                M = fmaxf(M, xs[jj - 1][ii    ]);
                M = fmaxf(M, xs[jj - 1][ii + 1]);
                M = fmaxf(M, xs[jj    ][ii - 1]);
                M = fmaxf(M, xs[jj    ][ii    ]);
                M = fmaxf(M, xs[jj    ][ii + 1]);
                M = fmaxf(M, xs[jj + 1][ii - 1]);
                M = fmaxf(M, xs[jj + 1][ii    ]);
                M = fmaxf(M, xs[jj + 1][ii + 1]);
                xx[k] = xs[jj][ii];
                int r = r0 + jj - 1, c = c0 + ii - 1;
                gd[k] = good[r * WW + c];
                pos[k] = __fsub_rn(__fmul_rn(M, gd[k]), xx[k]) > 0.05f;
                unsigned rowmask = __ballot_sync(0xffffffffu, pos[k]);
                if (tx == 0) s_rowpos[ty + k * 8] = rowmask;
            }
            int any = __syncthreads_or((pos[0] || pos[1]) ? 1 : 0);

            if (!any) {
                // no update possible -> refresh out buffer only if stale
                if (selfchg) {
                    #pragma unroll
                    for (int k = 0; k < 2; k++) {
                        int jj = 1 + ty + k * 8, ii = 1 + tx;
                        int r = r0 + jj - 1, c = c0 + ii - 1;
                        xo[r * WW + c] = xx[k];
                    }
                }
                if (tid == 0) {
                    if ((s_pos[by] >> bx) & 1ull)
                        atomicAnd(&g_posmask[by], ~(1ull << bx));
                }
                continue;
            }

            // ==== fill noised tile, cipher gated on pos-mask dilated 1 px ====
            #pragma unroll
            for (int k = 0; k < 3; k++) {
                int s = tid + k * 256;
                bool sv = s < NSLOT;
                int ss = sv ? s : 0;
                int j = ss / SW, ii = ss % SW;
                float x = sv ? xs[j][ii] : 0.0f;
                unsigned rm = 0;
                #pragma unroll
                for (int dr = 0; dr < 3; dr++) {
                    int cr = j - 2 + dr;
                    if (cr >= 0 && cr < TH) rm |= s_rowpos[cr];
                }
                unsigned long long rm2 = ((unsigned long long)rm) << 2;
                bool needc = (((rm2 >> ii) & 7ull) != 0ull) && (x > 0.0f);
                float y1 = 0.0f;
                if (__ballot_sync(0xffffffffu, needc)) {
                    int r = r0 - 1 + j, c = c0 - 1 + ii;
                    uint32_t p = (uint32_t)(min(max(r, 0), HH - 1) * WW +
                                            min(max(c, 0), WW - 1));
                    float u = bits_to_uniform(pbits(k1a, k1b, p));
                    float f = __fadd_rn(0.9999f, __fmul_rn(1e-4f, u));
                    y1 = __fmul_rn(x, f);
                }
                if (sv) ys[j][ii] = y1;
            }
            __syncthreads();

            // ==== maxpool + coin (cipher gated on pos) + write ====
            int chg = 0;
            #pragma unroll
            for (int k = 0; k < 2; k++) {
                int jj = 1 + ty + k * 8, ii = 1 + tx;
                float m = ys[jj - 1][ii - 1];
                m = fmaxf(m, ys[jj - 1][ii    ]);
                m = fmaxf(m, ys[jj - 1][ii + 1]);
                m = fmaxf(m, ys[jj    ][ii - 1]);
                m = fmaxf(m, ys[jj    ][ii    ]);
                m = fmaxf(m, ys[jj    ][ii + 1]);
                m = fmaxf(m, ys[jj + 1][ii - 1]);
                m = fmaxf(m, ys[jj + 1][ii    ]);
                m = fmaxf(m, ys[jj + 1][ii + 1]);

                int r = r0 + jj - 1, c = c0 + ii - 1;
                uint32_t p = (uint32_t)(r * WW + c);
                float y4 = 0.0f;
                if (__ballot_sync(0xffffffffu, pos[k])) {
                    uint32_t bits = pbits(k2a, k2b, p);
                    bool coin = ((bits >> 9) > 0x400000u);   // u > 0.5 strictly
                    if (coin && m > 0.0f) y4 = __fmul_rn(m, gd[k]);
                }
                float d  = __fsub_rn(y4, xx[k]);
                float y5 = (d > 0.05f) ? y4 : 0.0f;
                float out = fmaxf(y5, xx[k]);
                xo[p] = out;
                chg |= (out != xx[k]) ? 1 : 0;
            }
            int anychg = __syncthreads_or(chg);
            if (tid == 0) {
                unsigned long long bit = 1ull << bx;
                if (anychg) atomicOr(&g_chmask[cur][by], bit);
                if (!((s_pos[by] >> bx) & 1ull)) atomicOr(&g_posmask[by], bit);
            }
        }
        if (sawNeed && tid == 0) g_needflag[cur] = 1;   // idempotent store

        grid_barrier(nblocks, prev, cur);
    }
}

// ---------------------------------------------------------------------------
// Host: size grid for guaranteed co-residency, single launch.
// ---------------------------------------------------------------------------
extern "C" void kernel_launch(void* const* d_in, const int* in_sizes, int n_in,
                              void* d_out, int out_size) {
    const float* seed = (const float*)d_in[0];
    const float* hab  = (const float*)d_in[1];
    const float* good = (const float*)d_in[2];
    float* xout = (float*)d_out;

    int dev = 0;
    cudaGetDevice(&dev);
    int nsm = 148;
    cudaDeviceGetAttribute(&nsm, cudaDevAttrMultiProcessorCount, dev);
    int occ = 0;
    cudaOccupancyMaxActiveBlocksPerMultiprocessor(&occ, persist_kernel, 256, 0);
    if (occ < 1) occ = 1;
    int grid = nsm * occ;
    if (grid > NB) grid = NB;

    persist_kernel<<<grid, 256>>>(seed, hab, good, xout, grid);
}

// round 6
// speedup vs baseline: 1.6992x; 1.6992x over previous
#include <cuda_runtime.h>
#include <stdint.h>

#define HH 2048
#define WW 2048
#define NPIX (HH * WW)

#define TW 32                    // tile width
#define TH 16                    // tile height
#define SW (TW + 2)              // 34 (halo)
#define SH (TH + 2)              // 18 (halo)
#define NSLOT (SW * SH)          // 612

#define NBX 64                   // tiles per row (bits in a mask word)
#define NBY 128                  // tile rows
#define NB  (NBX * NBY)          // 8192
#define TILES_PER_BLOCK 4
#define STEP_GRID (NB / TILES_PER_BLOCK)   // 2048

typedef unsigned long long ull;

__device__ float g_scratch[NPIX];
__device__ ull g_chmask[3][NBY];   // changed bits, 3-parity rotation
__device__ ull g_posmask[NBY];     // possible bits

// ---------------------------------------------------------------------------
// Threefry-2x32, 20 rounds — exact transcription of jax._src.prng
// ---------------------------------------------------------------------------
__host__ __device__ __forceinline__ uint32_t rotl32(uint32_t v, uint32_t r) {
#ifdef __CUDA_ARCH__
    return __funnelshift_l(v, v, r);
#else
    return (v << r) | (v >> (32u - r));
#endif
}

__host__ __device__ __forceinline__ void tf2x32(uint32_t k0, uint32_t k1,
                                                uint32_t x0, uint32_t x1,
                                                uint32_t& o0, uint32_t& o1) {
    uint32_t ks2 = k0 ^ k1 ^ 0x1BD11BDAu;
    x0 += k0; x1 += k1;
#define TF_R(r) { x0 += x1; x1 = rotl32(x1, r); x1 ^= x0; }
    TF_R(13u) TF_R(15u) TF_R(26u) TF_R(6u)
    x0 += k1;  x1 += ks2 + 1u;
    TF_R(17u) TF_R(29u) TF_R(16u) TF_R(24u)
    x0 += ks2; x1 += k0 + 2u;
    TF_R(13u) TF_R(15u) TF_R(26u) TF_R(6u)
    x0 += k0;  x1 += k1 + 3u;
    TF_R(17u) TF_R(29u) TF_R(16u) TF_R(24u)
    x0 += k1;  x1 += ks2 + 4u;
    TF_R(13u) TF_R(15u) TF_R(26u) TF_R(6u)
    x0 += ks2; x1 += k0 + 5u;
#undef TF_R
    o0 = x0; o1 = x1;
}

// Partitionable-mode random bits for flat index p: counter=(0,p); bits=o0^o1
__device__ __forceinline__ uint32_t pbits(uint32_t k0, uint32_t k1, uint32_t p) {
    uint32_t o0, o1;
    tf2x32(k0, k1, 0u, p, o0, o1);
    return o0 ^ o1;
}

__device__ __forceinline__ float bits_to_uniform(uint32_t bits) {
    return __fsub_rn(__uint_as_float((bits >> 9) | 0x3f800000u), 1.0f);
}

// ---------------------------------------------------------------------------
// x0 = seed * habitat * goodness  (+ reset masks)
// ---------------------------------------------------------------------------
__global__ void init_kernel(const float* __restrict__ seed,
                            const float* __restrict__ hab,
                            const float* __restrict__ good,
                            float* __restrict__ xout) {
    int idx = blockIdx.x * blockDim.x + threadIdx.x;
    if (idx < NPIX / 4) {
        const float4 s = ((const float4*)seed)[idx];
        const float4 h = ((const float4*)hab)[idx];
        const float4 g = ((const float4*)good)[idx];
        float4 o;
        o.x = __fmul_rn(__fmul_rn(s.x, h.x), g.x);
        o.y = __fmul_rn(__fmul_rn(s.y, h.y), g.y);
        o.z = __fmul_rn(__fmul_rn(s.z, h.z), g.z);
        o.w = __fmul_rn(__fmul_rn(s.w, h.w), g.w);
        ((float4*)xout)[idx] = o;
    }
    if (idx < NBY) {
        g_chmask[2][idx] = ~0ull;   // prev parity of iter 0 -> force all tiles
        g_chmask[0][idx] = 0ull;
        g_chmask[1][idx] = 0ull;
        g_posmask[idx]   = 0ull;
    }
}

// ---------------------------------------------------------------------------
// One spread step. Each block owns 4 adjacent tiles in one tile-row; the
// need-check is inlined from the bitmasks (no flag kernel, no worklist).
//   y1 = x * (0.9999 + 1e-4*u1); y2 = maxpool3x3(y1); y3 = y2*(u2>0.5);
//   y4 = y3*goodness; x' = max(y4*((y4-x) > 0.05), x)
// Cell-level skip: "possible" iff fsub(fmul(max3x3(x),good),x) > 0.05
// (exact float upper bound since the noise factor <= 1.0f).
// ---------------------------------------------------------------------------
__global__ __launch_bounds__(256)
void step_kernel(const float* __restrict__ xin, float* __restrict__ xout,
                 const float* __restrict__ good,
                 uint32_t k1a, uint32_t k1b, uint32_t k2a, uint32_t k2b,
                 int prev, int cur, int nxt) {
    __shared__ float xs[SH][SW];     // raw x (tile + halo)
    __shared__ float ys[SH][SW];     // noised x (maxpool operand)
    __shared__ unsigned s_rowpos[TH];

    const int tid = threadIdx.x;
    const int tx = tid & 31;
    const int ty = tid >> 5;                     // 0..7

    // zero the next-parity mask row (not read or written this launch)
    if (blockIdx.x < NBY && tid == 0) g_chmask[nxt][blockIdx.x] = 0ull;

    const int tbase = blockIdx.x * TILES_PER_BLOCK;
    const int by  = tbase >> 6;
    const int bx0 = tbase & 63;

    // uniform mask loads (LDG broadcast; shared by all 4 tiles)
    ull nbm = g_chmask[prev][by];
    const ull chm = nbm;
    if (by > 0)       nbm |= g_chmask[prev][by - 1];
    if (by < NBY - 1) nbm |= g_chmask[prev][by + 1];
    const ull posw = g_posmask[by];

    #pragma unroll
    for (int kt = 0; kt < TILES_PER_BLOCK; kt++) {
        const int bx = bx0 + kt;
        const ull colm = (bx == 0) ? 3ull : (7ull << (bx - 1));
        const bool need = ((nbm & colm) != 0ull) || (((posw >> bx) & 1ull) != 0ull);
        if (!need) continue;                     // uniform across block

        const int selfchg = (int)((chm >> bx) & 1ull);
        const int c0 = bx * TW, r0 = by * TH;

        __syncthreads();                         // smem reuse barrier

        // ==== load raw x tile + halo ====
        #pragma unroll
        for (int k = 0; k < 3; k++) {
            int s = tid + k * 256;
            if (s < NSLOT) {
                int j = s / SW, ii = s % SW;
                int r = r0 - 1 + j, c = c0 - 1 + ii;
                bool ok = (r >= 0) && (r < HH) && (c >= 0) && (c < WW);
                xs[j][ii] = ok ? xin[r * WW + c] : 0.0f;
            }
        }
        __syncthreads();

        // ==== per-cell possible upper bound ====
        float xx[2], gd[2];
        bool  pos[2];
        #pragma unroll
        for (int k = 0; k < 2; k++) {
            int jj = 1 + ty + k * 8, ii = 1 + tx;
            float M = xs[jj - 1][ii - 1];
            M = fmaxf(M, xs[jj - 1][ii    ]);
            M = fmaxf(M, xs[jj - 1][ii + 1]);
            M = fmaxf(M, xs[jj    ][ii - 1]);
            M = fmaxf(M, xs[jj    ][ii    ]);
            M = fmaxf(M, xs[jj    ][ii + 1]);
            M = fmaxf(M, xs[jj + 1][ii - 1]);
            M = fmaxf(M, xs[jj + 1][ii    ]);
            M = fmaxf(M, xs[jj + 1][ii + 1]);
            xx[k] = xs[jj][ii];
            int r = r0 + jj - 1, c = c0 + ii - 1;
            gd[k] = good[r * WW + c];
            pos[k] = __fsub_rn(__fmul_rn(M, gd[k]), xx[k]) > 0.05f;
            unsigned rowmask = __ballot_sync(0xffffffffu, pos[k]);
            if (tx == 0) s_rowpos[ty + k * 8] = rowmask;
        }
        int any = __syncthreads_or((pos[0] || pos[1]) ? 1 : 0);

        if (!any) {
            // no update possible -> refresh out buffer only if stale
            if (selfchg) {
                #pragma unroll
                for (int k = 0; k < 2; k++) {
                    int jj = 1 + ty + k * 8, ii = 1 + tx;
                    int r = r0 + jj - 1, c = c0 + ii - 1;
                    xout[r * WW + c] = xx[k];
                }
            }
            if (tid == 0 && ((posw >> bx) & 1ull))
                atomicAnd(&g_posmask[by], ~(1ull << bx));
            continue;
        }

        // ==== fill noised tile, cipher gated on pos-mask dilated 1 px ====
        #pragma unroll
        for (int k = 0; k < 3; k++) {
            int s = tid + k * 256;
            bool sv = s < NSLOT;
            int ss = sv ? s : 0;
            int j = ss / SW, ii = ss % SW;
            float x = sv ? xs[j][ii] : 0.0f;
            unsigned rm = 0;
            #pragma unroll
            for (int dr = 0; dr < 3; dr++) {
                int cr = j - 2 + dr;
                if (cr >= 0 && cr < TH) rm |= s_rowpos[cr];
            }
            ull rm2 = ((ull)rm) << 2;
            bool needc = (((rm2 >> ii) & 7ull) != 0ull) && (x > 0.0f);
            float y1 = 0.0f;
            if (__ballot_sync(0xffffffffu, needc)) {
                int r = r0 - 1 + j, c = c0 - 1 + ii;
                uint32_t p = (uint32_t)(min(max(r, 0), HH - 1) * WW +
                                        min(max(c, 0), WW - 1));
                float u = bits_to_uniform(pbits(k1a, k1b, p));
                float f = __fadd_rn(0.9999f, __fmul_rn(1e-4f, u));
                y1 = __fmul_rn(x, f);
            }
            if (sv) ys[j][ii] = y1;
        }
        __syncthreads();

        // ==== maxpool + coin (cipher gated on pos) + write ====
        int chg = 0;
        #pragma unroll
        for (int k = 0; k < 2; k++) {
            int jj = 1 + ty + k * 8, ii = 1 + tx;
            float m = ys[jj - 1][ii - 1];
            m = fmaxf(m, ys[jj - 1][ii    ]);
            m = fmaxf(m, ys[jj - 1][ii + 1]);
            m = fmaxf(m, ys[jj    ][ii - 1]);
            m = fmaxf(m, ys[jj    ][ii    ]);
            m = fmaxf(m, ys[jj    ][ii + 1]);
            m = fmaxf(m, ys[jj + 1][ii - 1]);
            m = fmaxf(m, ys[jj + 1][ii    ]);
            m = fmaxf(m, ys[jj + 1][ii + 1]);

            int r = r0 + jj - 1, c = c0 + ii - 1;
            uint32_t p = (uint32_t)(r * WW + c);
            float y4 = 0.0f;
            if (__ballot_sync(0xffffffffu, pos[k])) {
                uint32_t bits = pbits(k2a, k2b, p);
                bool coin = ((bits >> 9) > 0x400000u);   // u > 0.5 strictly
                if (coin && m > 0.0f) y4 = __fmul_rn(m, gd[k]);
            }
            float d  = __fsub_rn(y4, xx[k]);
            float y5 = (d > 0.05f) ? y4 : 0.0f;
            float out = fmaxf(y5, xx[k]);
            xout[p] = out;
            chg |= (out != xx[k]) ? 1 : 0;
        }
        int anychg = __syncthreads_or(chg);
        if (tid == 0) {
            ull bit = 1ull << bx;
            if (anychg) atomicOr(&g_chmask[cur][by], bit);
            if (!((posw >> bx) & 1ull)) atomicOr(&g_posmask[by], bit);
        }
    }
}

// ---------------------------------------------------------------------------
// Host: per-iteration key schedule (fold_in + partitionable split), ping-pong
// data buffers, 3-parity changed masks. 101 launches total.
// ---------------------------------------------------------------------------
extern "C" void kernel_launch(void* const* d_in, const int* in_sizes, int n_in,
                              void* d_out, int out_size) {
    const float* seed = (const float*)d_in[0];
    const float* hab  = (const float*)d_in[1];
    const float* good = (const float*)d_in[2];
    float* xout = (float*)d_out;

    float* scratch = nullptr;
    cudaGetSymbolAddress((void**)&scratch, g_scratch);

    init_kernel<<<(NPIX / 4 + 255) / 256, 256>>>(seed, hab, good, xout);

    for (int i = 0; i < 100; i++) {
        // fold_in(key(42)=(0,42), i) = cipher((0,42), (0,i))
        uint32_t f0, f1;
        tf2x32(0u, 42u, 0u, (uint32_t)i, f0, f1);
        // partitionable split: k1 = cipher(f,(0,0)), k2 = cipher(f,(0,1))
        uint32_t k1a, k1b, k2a, k2b;
        tf2x32(f0, f1, 0u, 0u, k1a, k1b);
        tf2x32(f0, f1, 0u, 1u, k2a, k2b);

        const int cur = i % 3, prev = (i + 2) % 3, nxt = (i + 1) % 3;
        const float* xin = (i & 1) ? scratch : xout;
        float*       xo  = (i & 1) ? xout    : scratch;

        step_kernel<<<STEP_GRID, 256>>>(xin, xo, good, k1a, k1b, k2a, k2b,
                                        prev, cur, nxt);
    }
    // i = 99 (odd) wrote into xout -> final state lands in d_out
}